// round 17
// baseline (speedup 1.0000x reference)
#include <cuda_runtime.h>
#include <cuda_fp16.h>
#include <cstdint>

#define BSZ   256
#define MM    128
#define NN    1024
#define ITERS 100
#define ALPHA 0.1f

__device__ __half g_Ah[(size_t)BSZ * MM * NN];
__device__ float  g_C [(size_t)BSZ * MM * MM];   // AAT -> inverse (in place)

__device__ __forceinline__ uint32_t smem_u32(const void* p) {
    uint32_t a;
    asm("{ .reg .u64 t; cvta.to.shared.u64 t, %1; cvt.u32.u64 %0, t; }" : "=r"(a) : "l"(p));
    return a;
}
__device__ __forceinline__ uint32_t mapa_rank(uint32_t addr, uint32_t trank) {
    uint32_t r;
    asm("mapa.shared::cluster.u32 %0, %1, %2;" : "=r"(r) : "r"(addr), "r"(trank));
    return r;
}
__device__ __forceinline__ void cluster_sync_() {
    asm volatile("barrier.cluster.arrive.aligned;" ::: "memory");
    asm volatile("barrier.cluster.wait.aligned;"   ::: "memory");
}
__device__ __forceinline__ void st_cluster_f32(uint32_t addr, float v) {
    asm volatile("st.shared::cluster.f32 [%0], %1;" :: "r"(addr), "f"(v) : "memory");
}
__device__ __forceinline__ void mbar_init(uint32_t a, uint32_t c) {
    asm volatile("mbarrier.init.shared.b64 [%0], %1;" :: "r"(a), "r"(c) : "memory");
}
__device__ __forceinline__ void mbar_arrive_remote(uint32_t ra) {
    asm volatile("mbarrier.arrive.release.cluster.shared::cluster.b64 _, [%0];" :: "r"(ra) : "memory");
}
__device__ __forceinline__ void mbar_wait_acq(uint32_t mb, uint32_t par) {
    asm volatile(
        "{\n\t.reg .pred P;\n\t"
        "WL%=:\n\t"
        "mbarrier.try_wait.parity.acquire.cluster.shared::cta.b64 P, [%0], %1, 0x989680;\n\t"
        "@P bra.uni WD%=;\n\t"
        "bra.uni WL%=;\n\t"
        "WD%=:\n\t}" :: "r"(mb), "r"(par) : "memory");
}
__device__ __forceinline__ void ldsm_x4(uint32_t& a0, uint32_t& a1, uint32_t& a2, uint32_t& a3, uint32_t addr) {
    asm volatile("ldmatrix.sync.aligned.m8n8.x4.shared.b16 {%0,%1,%2,%3}, [%4];"
                 : "=r"(a0), "=r"(a1), "=r"(a2), "=r"(a3) : "r"(addr));
}
__device__ __forceinline__ void ldsm_x4t(uint32_t& a0, uint32_t& a1, uint32_t& a2, uint32_t& a3, uint32_t addr) {
    asm volatile("ldmatrix.sync.aligned.m8n8.x4.trans.shared.b16 {%0,%1,%2,%3}, [%4];"
                 : "=r"(a0), "=r"(a1), "=r"(a2), "=r"(a3) : "r"(addr));
}
__device__ __forceinline__ void mma16816(float& c0, float& c1, float& c2, float& c3,
                                         uint32_t a0, uint32_t a1, uint32_t a2, uint32_t a3,
                                         uint32_t b0, uint32_t b1) {
    asm volatile("mma.sync.aligned.m16n8k16.row.col.f32.f16.f16.f32 "
                 "{%0,%1,%2,%3},{%4,%5,%6,%7},{%8,%9},{%0,%1,%2,%3};"
                 : "+f"(c0), "+f"(c1), "+f"(c2), "+f"(c3)
                 : "r"(a0), "r"(a1), "r"(a2), "r"(a3), "r"(b0), "r"(b1));
}

// --------------------------------------------------------------------------
// k_aat (HMMA, fused fp32->fp16 convert) — verified R15/R16
// --------------------------------------------------------------------------
#define AT_PITCH_B 272
__global__ void __launch_bounds__(256) k_aat(const float* __restrict__ A32) {
    __shared__ __half tile[128 * (AT_PITCH_B / 2)];
    const int b = blockIdx.x, t = threadIdx.x, w = t >> 5, l = t & 31;
    const uint32_t tbase = smem_u32(tile);
    uint2* gah = (uint2*)(g_Ah + (size_t)b * MM * NN);

    float acc[16][4];
#pragma unroll
    for (int nt = 0; nt < 16; nt++)
#pragma unroll
        for (int q = 0; q < 4; q++) acc[nt][q] = 0.0f;

    const int m0 = w * 16;
    const uint32_t aAddr = tbase + (uint32_t)(m0 + (l & 15)) * AT_PITCH_B
                         + (uint32_t)((l >> 4) << 4);
    const int bg = l >> 3;
    const uint32_t bAddr0 = tbase + (uint32_t)((l & 7) + ((bg >> 1) << 3)) * AT_PITCH_B
                          + (uint32_t)((bg & 1) << 4);

    for (int kc = 0; kc < 8; kc++) {
#pragma unroll
        for (int q = 0; q < 16; q++) {
            int i = t + 256 * q, r = i >> 5, c4 = i & 31;
            float4 v = *(const float4*)(A32 + ((size_t)(b * MM + r)) * NN + kc * 128 + c4 * 4);
            uint2 hv;
            __half2 h0 = __floats2half2_rn(v.x, v.y);
            __half2 h1 = __floats2half2_rn(v.z, v.w);
            hv.x = *(uint32_t*)&h0; hv.y = *(uint32_t*)&h1;
            *(uint2*)((char*)tile + r * AT_PITCH_B + c4 * 8) = hv;
            gah[(size_t)r * 256 + kc * 32 + c4] = hv;
        }
        __syncthreads();

#pragma unroll
        for (int kt = 0; kt < 8; kt++) {
            uint32_t a0, a1, a2, a3;
            ldsm_x4(a0, a1, a2, a3, aAddr + (uint32_t)(kt * 32));
#pragma unroll
            for (int nt = 0; nt < 16; nt += 2) {
                uint32_t r0, r1, r2, r3;
                ldsm_x4(r0, r1, r2, r3,
                        bAddr0 + (uint32_t)(nt * 8) * AT_PITCH_B + (uint32_t)(kt * 32));
                mma16816(acc[nt][0],   acc[nt][1],   acc[nt][2],   acc[nt][3],
                         a0, a1, a2, a3, r0, r1);
                mma16816(acc[nt+1][0], acc[nt+1][1], acc[nt+1][2], acc[nt+1][3],
                         a0, a1, a2, a3, r2, r3);
            }
        }
        __syncthreads();
    }

    float* Cb = g_C + (size_t)b * MM * MM;
    const int r0 = m0 + (l >> 2), c0 = 2 * (l & 3);
#pragma unroll
    for (int nt = 0; nt < 16; nt++) {
        *(float2*)&Cb[(size_t)r0 * MM + nt * 8 + c0]       = make_float2(acc[nt][0], acc[nt][1]);
        *(float2*)&Cb[(size_t)(r0 + 8) * MM + nt * 8 + c0] = make_float2(acc[nt][2], acc[nt][3]);
    }
}

// --------------------------------------------------------------------------
// k_inv: BLOCKED Gauss-Jordan (rank-8) — verified R16
// --------------------------------------------------------------------------
__global__ void __launch_bounds__(512) k_inv() {
    extern __shared__ float sm[];
    float* sM = sm;              // 16384
    float* sG = sm + 16384;      // 1024
    float* sR = sm + 17408;      // 1024
    float* sB = sm + 18432;      // 64
    const int b = blockIdx.x, t = threadIdx.x;
    float* Cb = g_C + (size_t)b * MM * MM;

    for (int i = t; i < 4096; i += 512) ((float4*)sM)[i] = ((const float4*)Cb)[i];
    __syncthreads();

    for (int blk = 0; blk < 16; blk++) {
        const int k0 = blk * 8;
        if (t < 256) {
            int i = t >> 1, q = t & 1;
            *(float4*)&sG[i * 8 + 4 * q] = *(const float4*)&sM[i * 128 + k0 + 4 * q];
        }
        __syncthreads();

        if (t < 32) {
            sB[t]      = sG[(k0 + (t >> 3)) * 8 + (t & 7)];
            sB[t + 32] = sG[(k0 + 4 + (t >> 3)) * 8 + (t & 7)];
            __syncwarp();
#pragma unroll
            for (int k = 0; k < 8; k++) {
                float ipiv = 1.0f / sB[k * 8 + k];
                int r0 = t >> 3, c0 = t & 7, r1 = r0 + 4;
                float v0 = sB[t], v1 = sB[t + 32];
                float f0 = sB[r0 * 8 + k], f1 = sB[r1 * 8 + k];
                float mk = sB[k * 8 + c0];
                __syncwarp();
                float n0, n1;
                if (r0 == k) n0 = (c0 == k) ? ipiv : v0 * ipiv;
                else         n0 = (c0 == k) ? -f0 * ipiv : v0 - f0 * (mk * ipiv);
                if (r1 == k) n1 = (c0 == k) ? ipiv : v1 * ipiv;
                else         n1 = (c0 == k) ? -f1 * ipiv : v1 - f1 * (mk * ipiv);
                sB[t] = n0; sB[t + 32] = n1;
                __syncwarp();
            }
        }
        __syncthreads();

        {
            int idx = 2 * t;
            int r = idx >> 7, j = idx & 127;
            float a0 = 0.f, a1 = 0.f;
#pragma unroll
            for (int c = 0; c < 8; c++) {
                float bv = sB[r * 8 + c];
                float2 mrow = *(const float2*)&sM[(k0 + c) * 128 + j];
                a0 += bv * mrow.x;
                a1 += bv * mrow.y;
            }
            if (j     >= k0 && j     < k0 + 8) a0 = sB[r * 8 + (j - k0)];
            if (j + 1 >= k0 && j + 1 < k0 + 8) a1 = sB[r * 8 + (j + 1 - k0)];
            *(float2*)&sR[r * 128 + j] = make_float2(a0, a1);
        }
        __syncthreads();

        {
            int idx = 2 * t;
            int r = idx >> 7, j = idx & 127;
            *(float2*)&sM[(k0 + r) * 128 + j] = *(const float2*)&sR[r * 128 + j];
        }
        {
            int j4 = t & 31;
            int i0 = (t >> 5) * 8;
            float4 r4[8];
#pragma unroll
            for (int c = 0; c < 8; c++) r4[c] = *(const float4*)&sR[c * 128 + 4 * j4];
            const bool inb = (4 * j4 >= k0) && (4 * j4 < k0 + 8);
#pragma unroll
            for (int ii = 0; ii < 8; ii++) {
                int i = i0 + ii;
                if (i >= k0 && i < k0 + 8) continue;
                float4 g0 = *(const float4*)&sG[i * 8];
                float4 g1 = *(const float4*)&sG[i * 8 + 4];
                float4 a = inb ? make_float4(0.f, 0.f, 0.f, 0.f)
                               : *(const float4*)&sM[i * 128 + 4 * j4];
                a.x -= g0.x*r4[0].x + g0.y*r4[1].x + g0.z*r4[2].x + g0.w*r4[3].x
                     + g1.x*r4[4].x + g1.y*r4[5].x + g1.z*r4[6].x + g1.w*r4[7].x;
                a.y -= g0.x*r4[0].y + g0.y*r4[1].y + g0.z*r4[2].y + g0.w*r4[3].y
                     + g1.x*r4[4].y + g1.y*r4[5].y + g1.z*r4[6].y + g1.w*r4[7].y;
                a.z -= g0.x*r4[0].z + g0.y*r4[1].z + g0.z*r4[2].z + g0.w*r4[3].z
                     + g1.x*r4[4].z + g1.y*r4[5].z + g1.z*r4[6].z + g1.w*r4[7].z;
                a.w -= g0.x*r4[0].w + g0.y*r4[1].w + g0.z*r4[2].w + g0.w*r4[3].w
                     + g1.x*r4[4].w + g1.y*r4[5].w + g1.z*r4[6].w + g1.w*r4[7].w;
                *(float4*)&sM[i * 128 + 4 * j4] = a;
            }
        }
        __syncthreads();
    }

    for (int i = t; i < 4096; i += 512) ((float4*)Cb)[i] = ((const float4*)sM)[i];
}

// Iterations: R16 core, ONE change: packed uint4 b-fragments (Y4/U4),
// LDS.128 instead of 4x LDS.32 in both HMMA passes. ---------------------------
#define APAD_U4  65
#define OFF_C    0                     // 16384 f
#define OFF_A    16384                 // 33280 w (128*260 u32)
#define OFF_Y4   49664                 // 512 w : 128 uint4 {hi(kb),hi(kb+4),lo(kb),lo(kb+4)}
#define OFF_B    50176                 // 128 f
#define OFF_SR0  50304                 // 128 f
#define OFF_SR1  50432                 // 128 f
#define OFF_REM  50560                 // 256 f (peer partial, 2 bufs)
#define OFF_RT   50816                 // 128 f
#define OFF_U4   50944                 // 128 w : 32 uint4
#define OFF_CORR 51072                 // 512 f
#define OFF_MB   51584                 // 2 x u64 mbarriers
#define SMEM_WORDS 51588               // 206352 bytes

__global__ void __launch_bounds__(512, 1) __cluster_dims__(2, 1, 1)
k_iter(const float* __restrict__ bvec, const float* __restrict__ D1,
       const float* __restrict__ D2, float* __restrict__ out) {
    extern __shared__ float sm[];
    const int t = threadIdx.x, w = t >> 5, l = t & 31;
    const int b = blockIdx.x >> 1;
    const uint32_t rank = blockIdx.x & 1;
    const uint32_t sbase = smem_u32(sm);
    const uint32_t peer = mapa_rank(sbase, rank ^ 1u);
    const uint32_t aA = sbase + OFF_A * 4u;

    {   // load C, padded A-half, b
        float4* d = (float4*)(sm + OFF_C);
        const float4* s = (const float4*)(g_C + (size_t)b * MM * MM);
#pragma unroll
        for (int q = 0; q < 8; q++) d[t + 512 * q] = s[t + 512 * q];
        uint4* da = (uint4*)(sm + OFF_A);
        const uint4* sa = (const uint4*)(g_Ah + (size_t)b * MM * NN + (size_t)rank * 512);
#pragma unroll
        for (int q = 0; q < 16; q++) {
            int i = t + 512 * q, r = i >> 6, c4 = i & 63;
            da[r * APAD_U4 + c4] = sa[(size_t)r * 128 + c4];
        }
        if (t < 128) sm[OFF_B + t] = bvec[(size_t)b * MM + t];
        if (t == 0) {
            mbar_init(sbase + OFF_MB * 4u, 128);
            mbar_init(sbase + OFF_MB * 4u + 8u, 128);
        }
    }

    // per-thread state: t<256 owns local cols 2t, 2t+1
    float2 thr2 = make_float2(0.f, 0.f), dv2 = make_float2(0.f, 0.f);
    float2 z2 = make_float2(0.f, 0.f), xh2, yv2 = make_float2(0.f, 0.f);
    // packed-Y4 write slot for this thread (local half2 idx = kb + 4*slot)
    int ew_widx = 0, ew_slot = 0;
    if (t < 256) {
        float2 d1 = ((const float2*)(D1 + (size_t)b * NN + rank * 512))[t];
        float2 d2 = ((const float2*)(D2 + (size_t)b * NN + rank * 512))[t];
        thr2.x = ALPHA * fabsf(d1.x); thr2.y = ALPHA * fabsf(d1.y);
        dv2.x = 1.0f / (1.0f + 2.0f * ALPHA * d2.x * d2.x);
        dv2.y = 1.0f / (1.0f + 2.0f * ALPHA * d2.y * d2.y);
        int kh = t >> 7, local = t & 127;
        int kt = local >> 3, rem = local & 7;
        ew_widx = (kh * 64 + kt * 4 + (rem & 3)) * 4;
        ew_slot = (rem < 4) ? 0 : 1;
    }
    __syncthreads();
    cluster_sync_();

    // pass1 per-warp constants: warp w -> m-tile rows 16*(w&7), k-half w>>3
    const int p1_m0 = (w & 7) * 16, p1_kh = w >> 3;
    const uint32_t p1_addr = aA + (uint32_t)(p1_m0 + (l & 15)) * 1040u
                           + (uint32_t)(p1_kh * 512) + (uint32_t)((l >> 4) << 4);
    const int bc = l & 3;
    const uint32_t p2_rowoff = (uint32_t)((l & 7) + ((l >> 4) << 3)) * 1040u
                             + (uint32_t)((l & 8) << 1);

    for (int it = 0; it < ITERS; it++) {
        const int buf = it & 1;
        // --- elementwise: soft-threshold, y, split hi/lo, PACKED store ---
        if (t < 256) {
            float a0 = z2.x - thr2.x, c0 = z2.x + thr2.x;
            float a1 = z2.y - thr2.y, c1 = z2.y + thr2.y;
            xh2.x = (a0 > 0.f) ? a0 * dv2.x : ((c0 < 0.f) ? c0 * dv2.x : 0.f);
            xh2.y = (a1 > 0.f) ? a1 * dv2.y : ((c1 < 0.f) ? c1 * dv2.y : 0.f);
            yv2.x = 2.0f * xh2.x - z2.x;
            yv2.y = 2.0f * xh2.y - z2.y;
            __half2 hy = __floats2half2_rn(yv2.x, yv2.y);
            float2 fy = __half22float2(hy);
            __half2 ly = __floats2half2_rn(yv2.x - fy.x, yv2.y - fy.y);
            uint32_t* y4w = (uint32_t*)(sm + OFF_Y4) + ew_widx;
            y4w[ew_slot]     = *(uint32_t*)&hy;
            y4w[ew_slot + 2] = *(uint32_t*)&ly;
        }
        __syncthreads();                                   // bar1: y ready

        // --- pass 1 (HMMA, packed LDS.128 b-frags) ---
        {
            float ch0 = 0.f, ch1 = 0.f, ch2 = 0.f, ch3 = 0.f;
            float cl0 = 0.f, cl1 = 0.f, cl2 = 0.f, cl3 = 0.f;
            const uint4* y4 = (const uint4*)(sm + OFF_Y4) + p1_kh * 64 + bc;
            uint32_t addr = p1_addr;
#pragma unroll
            for (int kt = 0; kt < 16; kt++) {
                uint32_t a0, a1, a2, a3;
                ldsm_x4(a0, a1, a2, a3, addr);
                addr += 32u;
                uint4 yv = y4[kt * 4];
                mma16816(ch0, ch1, ch2, ch3, a0, a1, a2, a3, yv.x, yv.y);
                mma16816(cl0, cl1, cl2, cl3, a0, a1, a2, a3, yv.z, yv.w);
            }
            if ((l & 3) == 0) {
                float* srp = sm + (p1_kh ? OFF_SR1 : OFF_SR0);
                srp[p1_m0 + (l >> 2)]     = ch0 + cl0;
                srp[p1_m0 + 8 + (l >> 2)] = ch2 + cl2;
            }
        }
        __syncthreads();                                   // bar2: partials ready

        // --- exchange + r_total (t<128) ---
        if (t < 128) {
            float s = sm[OFF_SR0 + t] + sm[OFF_SR1 + t];
            st_cluster_f32(peer + (uint32_t)(OFF_REM + buf * 128 + t) * 4u, s);
            mbar_arrive_remote(peer + OFF_MB * 4u + 8u * buf);
            mbar_wait_acq(sbase + OFF_MB * 4u + 8u * buf, (uint32_t)((it >> 1) & 1));
            sm[OFF_RT + t] = s + sm[OFF_REM + buf * 128 + t] - sm[OFF_B + t];
        }
        __syncthreads();                                   // bar3: rt ready

        // --- u = C * rt (512 threads, 4/row, conflict-free), PACKED store ---
        {
            int i = t >> 2, q = t & 3, h0 = i & 7;
            float accu = 0.0f;
#pragma unroll
            for (int m = 0; m < 8; m++) {
                int j = 4 * (q + 4 * ((h0 + m) & 7));
                float4 c4 = *(const float4*)(sm + OFF_C + i * 128 + j);
                float4 r4 = *(const float4*)(sm + OFF_RT + j);
                accu += c4.x * r4.x + c4.y * r4.y + c4.z * r4.z + c4.w * r4.w;
            }
            accu += __shfl_xor_sync(0xffffffffu, accu, 1);
            accu += __shfl_xor_sync(0xffffffffu, accu, 2);
            float un = __shfl_down_sync(0xffffffffu, accu, 4);
            if ((t & 7) == 0) {
                __half2 hu = __floats2half2_rn(accu, un);
                float2 fu = __half22float2(hu);
                __half2 lu = __floats2half2_rn(accu - fu.x, un - fu.y);
                int idx = t >> 3;                           // u pair index [0,64)
                int kt = idx >> 3, rem = idx & 7;
                uint32_t* u4w = (uint32_t*)(sm + OFF_U4) + (kt * 4 + (rem & 3)) * 4;
                int slot = (rem < 4) ? 0 : 1;
                u4w[slot]     = *(uint32_t*)&hu;
                u4w[slot + 2] = *(uint32_t*)&lu;
            }
        }
        __syncthreads();                                   // bar4: u ready

        // --- pass 2 (HMMA trans, packed LDS.128 b-frags) ---
        {
            const uint4* u4 = (const uint4*)(sm + OFF_U4) + bc;
#pragma unroll
            for (int mi = 0; mi < 2; mi++) {
                int mt = 2 * w + mi, cc0 = mt * 16;
                float dh0 = 0.f, dh1 = 0.f, dh2 = 0.f, dh3 = 0.f;
                float dl0 = 0.f, dl1 = 0.f, dl2 = 0.f, dl3 = 0.f;
                uint32_t addr = aA + p2_rowoff + (uint32_t)(cc0 * 2);
#pragma unroll
                for (int kt = 0; kt < 8; kt++) {
                    uint32_t a0, a1, a2, a3;
                    ldsm_x4t(a0, a1, a2, a3, addr);
                    addr += 16u * 1040u;
                    uint4 uv = u4[kt * 4];
                    mma16816(dh0, dh1, dh2, dh3, a0, a1, a2, a3, uv.x, uv.y);
                    mma16816(dl0, dl1, dl2, dl3, a0, a1, a2, a3, uv.z, uv.w);
                }
                if ((l & 3) == 0) {
                    sm[OFF_CORR + cc0 + (l >> 2)]     = dh0 + dl0;
                    sm[OFF_CORR + cc0 + 8 + (l >> 2)] = dh2 + dl2;
                }
            }
        }
        __syncthreads();                                   // bar5: corr ready

        // --- epilogue: z' = x_half - corr, x_new = y - corr ---
        if (t < 256) {
            float2 cr = *(const float2*)(sm + OFF_CORR + 2 * t);
            z2.x = xh2.x - cr.x; z2.y = xh2.y - cr.y;
            yv2.x -= cr.x; yv2.y -= cr.y;                  // x_new
        }
    }

    if (t < 256)
        ((float2*)(out + (size_t)b * NN + rank * 512))[t] = yv2;
    cluster_sync_();
}

// --------------------------------------------------------------------------
extern "C" void kernel_launch(void* const* d_in, const int* in_sizes, int n_in,
                              void* d_out, int out_size) {
    const float* A  = (const float*)d_in[0];
    const float* bv = (const float*)d_in[1];
    const float* D1 = (const float*)d_in[2];
    const float* D2 = (const float*)d_in[3];
    float* out = (float*)d_out;

    cudaFuncSetAttribute(k_inv,  cudaFuncAttributeMaxDynamicSharedMemorySize, 73984);
    cudaFuncSetAttribute(k_iter, cudaFuncAttributeMaxDynamicSharedMemorySize, SMEM_WORDS * 4);

    k_aat<<<BSZ, 256>>>(A);        // fused convert + AAT
    k_inv<<<BSZ, 512, 73984>>>();
    k_iter<<<BSZ * 2, 512, SMEM_WORDS * 4>>>(bv, D1, D2, out);
}